// round 16
// baseline (speedup 1.0000x reference)
#include <cuda_runtime.h>
#include <cuda_bf16.h>
#include <cstdint>

#define N_RELS 64
#define REL_STRIDE4 3        // 3 float4 per relation = 48B (M row + beta in .w)
#define TPB 128              // threads per CTA
#define QPT 128              // quads per tile
#define P_BYTES (QPT * 48)   // 6144B prnt tile
#define C_BYTES (QPT * 48)   // 6144B child tile
#define STAGE_BYTES (P_BYTES + C_BYTES)   // 12288
#define DEPTH 2

static __device__ __forceinline__ unsigned smem_u32(const void *p) {
    return (unsigned)__cvta_generic_to_shared(p);
}
static __device__ __forceinline__ void mbar_init(unsigned a, unsigned cnt) {
    asm volatile("mbarrier.init.shared.b64 [%0], %1;" :: "r"(a), "r"(cnt) : "memory");
}
static __device__ __forceinline__ void mbar_expect_tx(unsigned a, unsigned bytes) {
    asm volatile("mbarrier.arrive.expect_tx.shared.b64 _, [%0], %1;"
                 :: "r"(a), "r"(bytes) : "memory");
}
static __device__ __forceinline__ void mbar_wait(unsigned a, unsigned phase) {
    asm volatile(
        "{\n\t.reg .pred P;\n"
        "LW_%=:\n\t"
        "mbarrier.try_wait.parity.acquire.cta.shared::cta.b64 P, [%0], %1, 0x989680;\n\t"
        "@P bra.uni LD_%=;\n\t"
        "bra.uni LW_%=;\n"
        "LD_%=:\n\t}"
        :: "r"(a), "r"(phase) : "memory");
}
// 1D bulk async copy global->shared, completion via mbarrier complete_tx.
static __device__ __forceinline__ void bulk_g2s(unsigned dst, const void *src,
                                                unsigned bytes, unsigned mbar) {
    asm volatile(
        "cp.async.bulk.shared::cluster.global.mbarrier::complete_tx::bytes "
        "[%0], [%1], %2, [%3];"
        :: "r"(dst), "l"(src), "r"(bytes), "r"(mbar) : "memory");
}

// Sparsemax for d=3 via closed-form threshold:
//   tau = max_k (cs_k - 1)/k  == reference's (cs[ksup-1]-1)/ksup
static __device__ __forceinline__ void sparsemax3(float x0, float x1, float x2,
                                                  float &o0, float &o1, float &o2) {
    float mx  = fmaxf(fmaxf(x0, x1), x2);
    float mn  = fminf(fminf(x0, x1), x2);
    float sum = x0 + x1 + x2;
    float t1 = mx - 1.0f;
    float t2 = (sum - mn - 1.0f) * 0.5f;
    float t3 = (sum - 1.0f) * (1.0f / 3.0f);
    float tau = fmaxf(t1, fmaxf(t2, t3));
    o0 = fmaxf(x0 - tau, 0.0f);
    o1 = fmaxf(x1 - tau, 0.0f);
    o2 = fmaxf(x2 - tau, 0.0f);
}

static __device__ __forceinline__ void row_compute(
    float p0, float p1, float p2,
    float h0, float h1, float h2,
    const float4 *__restrict__ relp,
    float zeps, float sf,
    float &a0, float &a1, float &a2)
{
    float4 m0 = relp[0];   // {M00,M01,M02, beta0}
    float4 m1 = relp[1];   // {M10,M11,M12, beta1}
    float4 m2 = relp[2];   // {M20,M21,M22, beta2}

    // c = M[rel] @ child
    float c0 = m0.x * h0 + m0.y * h1 + m0.z * h2;
    float c1 = m1.x * h0 + m1.y * h1 + m1.z * h2;
    float c2 = m2.x * h0 + m2.y * h1 + m2.z * h2;
    sparsemax3(c0, c1, c2, c0, c1, c2);
    // (second sparsemax is an exact identity on a simplex point — dropped)
    sparsemax3(p0, p1, p2, p0, p1, p2);

    // alpha = (1-b)*p + b*c == p + b*(c-p)
    a0 = p0 + m0.w * (c0 - p0);
    a1 = p1 + m1.w * (c1 - p1);
    a2 = p2 + m2.w * (c2 - p2);

    // entropy of clamped normalized mixture (base-2; ln2 folded into divide)
    float w0 = fmaxf(p0 + c0, zeps);
    float w1 = fmaxf(p1 + c1, zeps);
    float w2 = fmaxf(p2 + c2, zeps);
    float inv = __fdividef(1.0f, w0 + w1 + w2);
    w0 *= inv; w1 *= inv; w2 *= inv;
    float t2 = w0 * __log2f(w0) + w1 * __log2f(w1) + w2 * __log2f(w2); // < 0

    // sparsemax outputs sum to 1 => max comp >= 1/3 => pp*cc >= 1/81:
    // reference's max(nrm,1e-10) guard is provably inactive.
    float dot = p0 * c0 + p1 * c1 + p2 * c2;
    float pp  = p0 * p0 + p1 * p1 + p2 * p2;
    float cc  = c0 * c0 + c1 * c1 + c2 * c2;
    float rq  = rsqrtf(pp * cc);
    float cosv = 0.1f + dot * rq;
    float scale = __fdividef(sf * cosv, -0.69314718056f * t2);

    a0 = fmaxf(a0 * scale, 0.001f);
    a1 = fmaxf(a1 * scale, 0.001f);
    a2 = fmaxf(a2 * scale, 0.001f);
}

__global__ void __launch_bounds__(TPB, 8)
alpha_kernel(const float *__restrict__ prnt,
             const float *__restrict__ child,
             const float *__restrict__ Mg,
             const float *__restrict__ betag,
             const float *__restrict__ zeps_p,
             const float *__restrict__ sf_p,
             const int *__restrict__ rels,
             float *__restrict__ out,
             int n, int nquads, int ntiles)
{
    __shared__ __align__(128) unsigned char sStage[DEPTH][STAGE_BYTES];
    __shared__ float4 sRel[N_RELS * REL_STRIDE4];
    __shared__ __align__(8) unsigned long long sMbar[DEPTH];

    const int tid = threadIdx.x;

    // rel table: 3 float4 per rel = {M_row_i | beta_i}
    {
        float *sF = reinterpret_cast<float *>(sRel);
        for (int i = tid; i < N_RELS * 12; i += TPB) {
            int r = i / 12, j = i % 12;
            int row = j >> 2, c = j & 3;
            sF[r * 12 + j] = (c < 3) ? Mg[r * 9 + row * 3 + c]
                                     : betag[r * 3 + row];
        }
    }
    if (tid == 0) {
        mbar_init(smem_u32(&sMbar[0]), 1);
        mbar_init(smem_u32(&sMbar[1]), 1);
    }
    __syncthreads();   // table + barriers ready

    const float zeps = __ldg(zeps_p);
    const float sf   = __ldg(sf_p);
    const int G = gridDim.x;

    // producer: issue prnt+child of tile t into stage s (t < ntiles guaranteed)
    auto issue = [&](int t, int s) {
        int q0 = t * QPT;
        int qn = nquads - q0; if (qn > QPT) qn = QPT;   // >0
        unsigned pb = smem_u32(&sStage[s][0]);
        unsigned mb = smem_u32(&sMbar[s]);
        unsigned by = (unsigned)qn * 48u;
        mbar_expect_tx(mb, by * 2u);
        bulk_g2s(pb,           prnt  + (size_t)q0 * 12, by, mb);
        bulk_g2s(pb + P_BYTES, child + (size_t)q0 * 12, by, mb);
    };

    // prologue: fill both stages
    if (tid == 0) {
        if (blockIdx.x < ntiles)      issue(blockIdx.x, 0);
        if (blockIdx.x + G < ntiles)  issue(blockIdx.x + G, 1);
    }

    unsigned ph0 = 0, ph1 = 0;
    int s = 0;
    for (int t = blockIdx.x; t < ntiles; t += G) {
        int q = t * QPT + tid;
        bool act = q < nquads;

        // rels via direct LDG — only 4 regs held across the wait
        int4 r4;
        if (act) r4 = __ldcs(reinterpret_cast<const int4 *>(rels) + q);

        unsigned mb = smem_u32(&sMbar[s]);
        if (s == 0) { mbar_wait(mb, ph0); ph0 ^= 1u; }
        else        { mbar_wait(mb, ph1); ph1 ^= 1u; }

        if (act) {
            const float4 *sp = reinterpret_cast<const float4 *>(&sStage[s][0]) + tid * 3;
            const float4 *sc = reinterpret_cast<const float4 *>(&sStage[s][P_BYTES]) + tid * 3;
            float4 pA = sp[0], pB = sp[1], pC = sp[2];
            float4 cA = sc[0], cB = sc[1], cC = sc[2];

            float pv[12] = {pA.x, pA.y, pA.z, pA.w, pB.x, pB.y, pB.z, pB.w,
                            pC.x, pC.y, pC.z, pC.w};
            float cv[12] = {cA.x, cA.y, cA.z, cA.w, cB.x, cB.y, cB.z, cB.w,
                            cC.x, cC.y, cC.z, cC.w};
            int rr[4] = {r4.x, r4.y, r4.z, r4.w};
            float ov[12];
#pragma unroll
            for (int i = 0; i < 4; i++) {
                row_compute(pv[3 * i], pv[3 * i + 1], pv[3 * i + 2],
                            cv[3 * i], cv[3 * i + 1], cv[3 * i + 2],
                            &sRel[rr[i] * REL_STRIDE4], zeps, sf,
                            ov[3 * i], ov[3 * i + 1], ov[3 * i + 2]);
            }
            float4 *o4 = reinterpret_cast<float4 *>(out) + (size_t)q * 3;
            __stcs(o4 + 0, make_float4(ov[0], ov[1], ov[2],  ov[3]));
            __stcs(o4 + 1, make_float4(ov[4], ov[5], ov[6],  ov[7]));
            __stcs(o4 + 2, make_float4(ov[8], ov[9], ov[10], ov[11]));
        }

        __syncthreads();   // whole CTA done reading stage s
        if (tid == 0 && t + 2 * G < ntiles) issue(t + 2 * G, s);
        s ^= 1;
    }

    // scalar tail (n % 4 rows) — empty for N = 8,000,000 but kept general
    int rem = n - nquads * 4;
    int gidx = blockIdx.x * TPB + tid;
    if (gidx < rem) {
        int i = nquads * 4 + gidx;
        float a0, a1, a2;
        row_compute(prnt[3 * i], prnt[3 * i + 1], prnt[3 * i + 2],
                    child[3 * i], child[3 * i + 1], child[3 * i + 2],
                    &sRel[rels[i] * REL_STRIDE4], zeps, sf, a0, a1, a2);
        out[3 * i] = a0; out[3 * i + 1] = a1; out[3 * i + 2] = a2;
    }
}

extern "C" void kernel_launch(void* const* d_in, const int* in_sizes, int n_in,
                              void* d_out, int out_size) {
    // metadata order: prnt_probs, child_probs, M, beta, z_epsilon, scale_factor, rels, var_sfx
    const float *prnt  = (const float *)d_in[0];
    const float *child = (const float *)d_in[1];
    const float *Mg    = (const float *)d_in[2];
    const float *betag = (const float *)d_in[3];
    const float *zeps  = (const float *)d_in[4];
    const float *sf    = (const float *)d_in[5];
    const int   *rels  = (const int *)d_in[6];
    float *out = (float *)d_out;

    int n = in_sizes[6];
    int nquads = n / 4;
    int ntiles = (nquads + QPT - 1) / QPT;
    int maxb = 148 * 8;   // 8 CTAs/SM residency target
    int blocks = ntiles < maxb ? (ntiles > 0 ? ntiles : 1) : maxb;

    alpha_kernel<<<blocks, TPB>>>(prnt, child, Mg, betag, zeps, sf, rels,
                                  out, n, nquads, ntiles);
}

// round 17
// speedup vs baseline: 1.0234x; 1.0234x over previous
#include <cuda_runtime.h>
#include <cuda_bf16.h>
#include <cstdint>

#define N_RELS 64
#define REL_STRIDE4 3        // 3 float4 per relation = 48B (M row + beta in .w)
#define TPB 256              // threads per CTA
#define QPT 256              // quads per tile
#define C_BYTES (QPT * 48)   // 12288B child tile
#define R_BYTES (QPT * 16)   // 4096B rels tile
#define STAGE_BYTES (C_BYTES + R_BYTES)   // 16384
#define DEPTH 2

static __device__ __forceinline__ unsigned smem_u32(const void *p) {
    return (unsigned)__cvta_generic_to_shared(p);
}
static __device__ __forceinline__ void mbar_init(unsigned a, unsigned cnt) {
    asm volatile("mbarrier.init.shared.b64 [%0], %1;" :: "r"(a), "r"(cnt) : "memory");
}
static __device__ __forceinline__ void mbar_expect_tx(unsigned a, unsigned bytes) {
    asm volatile("mbarrier.arrive.expect_tx.shared.b64 _, [%0], %1;"
                 :: "r"(a), "r"(bytes) : "memory");
}
static __device__ __forceinline__ void mbar_wait(unsigned a, unsigned phase) {
    asm volatile(
        "{\n\t.reg .pred P;\n"
        "LW_%=:\n\t"
        "mbarrier.try_wait.parity.acquire.cta.shared::cta.b64 P, [%0], %1, 0x989680;\n\t"
        "@P bra.uni LD_%=;\n\t"
        "bra.uni LW_%=;\n"
        "LD_%=:\n\t}"
        :: "r"(a), "r"(phase) : "memory");
}
// 1D bulk async copy global->shared, completion via mbarrier complete_tx.
static __device__ __forceinline__ void bulk_g2s(unsigned dst, const void *src,
                                                unsigned bytes, unsigned mbar) {
    asm volatile(
        "cp.async.bulk.shared::cluster.global.mbarrier::complete_tx::bytes "
        "[%0], [%1], %2, [%3];"
        :: "r"(dst), "l"(src), "r"(bytes), "r"(mbar) : "memory");
}

// Sparsemax for d=3 via closed-form threshold:
//   tau = max_k (cs_k - 1)/k  == reference's (cs[ksup-1]-1)/ksup
static __device__ __forceinline__ void sparsemax3(float x0, float x1, float x2,
                                                  float &o0, float &o1, float &o2) {
    float mx  = fmaxf(fmaxf(x0, x1), x2);
    float mn  = fminf(fminf(x0, x1), x2);
    float sum = x0 + x1 + x2;
    float t1 = mx - 1.0f;
    float t2 = (sum - mn - 1.0f) * 0.5f;
    float t3 = (sum - 1.0f) * (1.0f / 3.0f);
    float tau = fmaxf(t1, fmaxf(t2, t3));
    o0 = fmaxf(x0 - tau, 0.0f);
    o1 = fmaxf(x1 - tau, 0.0f);
    o2 = fmaxf(x2 - tau, 0.0f);
}

static __device__ __forceinline__ void row_compute(
    float p0, float p1, float p2,
    float h0, float h1, float h2,
    const float4 *__restrict__ relp,
    float zeps, float sf,
    float &a0, float &a1, float &a2)
{
    float4 m0 = relp[0];   // {M00,M01,M02, beta0}
    float4 m1 = relp[1];   // {M10,M11,M12, beta1}
    float4 m2 = relp[2];   // {M20,M21,M22, beta2}

    // c = M[rel] @ child
    float c0 = m0.x * h0 + m0.y * h1 + m0.z * h2;
    float c1 = m1.x * h0 + m1.y * h1 + m1.z * h2;
    float c2 = m2.x * h0 + m2.y * h1 + m2.z * h2;
    sparsemax3(c0, c1, c2, c0, c1, c2);
    // (second sparsemax is an exact identity on a simplex point — dropped)
    sparsemax3(p0, p1, p2, p0, p1, p2);

    // alpha = (1-b)*p + b*c == p + b*(c-p)
    a0 = p0 + m0.w * (c0 - p0);
    a1 = p1 + m1.w * (c1 - p1);
    a2 = p2 + m2.w * (c2 - p2);

    // entropy of clamped normalized mixture (base-2; ln2 folded into divide)
    float w0 = fmaxf(p0 + c0, zeps);
    float w1 = fmaxf(p1 + c1, zeps);
    float w2 = fmaxf(p2 + c2, zeps);
    float inv = __fdividef(1.0f, w0 + w1 + w2);
    w0 *= inv; w1 *= inv; w2 *= inv;
    float t2 = w0 * __log2f(w0) + w1 * __log2f(w1) + w2 * __log2f(w2); // < 0

    // sparsemax outputs sum to 1 => max comp >= 1/3 => pp*cc >= 1/81:
    // reference's max(nrm,1e-10) guard is provably inactive.
    float dot = p0 * c0 + p1 * c1 + p2 * c2;
    float pp  = p0 * p0 + p1 * p1 + p2 * p2;
    float cc  = c0 * c0 + c1 * c1 + c2 * c2;
    float rq  = rsqrtf(pp * cc);
    float cosv = 0.1f + dot * rq;
    float scale = __fdividef(sf * cosv, -0.69314718056f * t2);

    a0 = fmaxf(a0 * scale, 0.001f);
    a1 = fmaxf(a1 * scale, 0.001f);
    a2 = fmaxf(a2 * scale, 0.001f);
}

__global__ void __launch_bounds__(TPB, 5)
alpha_kernel(const float *__restrict__ prnt,
             const float *__restrict__ child,
             const float *__restrict__ Mg,
             const float *__restrict__ betag,
             const float *__restrict__ zeps_p,
             const float *__restrict__ sf_p,
             const int *__restrict__ rels,
             float *__restrict__ out,
             int n, int nquads, int ntiles)
{
    __shared__ __align__(128) unsigned char sStage[DEPTH][STAGE_BYTES];
    __shared__ float4 sRel[N_RELS * REL_STRIDE4];
    __shared__ __align__(8) unsigned long long sMbar[DEPTH];

    const int tid = threadIdx.x;

    // rel table: 3 float4 per rel = {M_row_i | beta_i}
    {
        float *sF = reinterpret_cast<float *>(sRel);
        for (int i = tid; i < N_RELS * 12; i += TPB) {
            int r = i / 12, j = i % 12;
            int row = j >> 2, c = j & 3;
            sF[r * 12 + j] = (c < 3) ? Mg[r * 9 + row * 3 + c]
                                     : betag[r * 3 + row];
        }
    }
    if (tid == 0) {
        mbar_init(smem_u32(&sMbar[0]), 1);
        mbar_init(smem_u32(&sMbar[1]), 1);
    }
    __syncthreads();   // table + barriers ready

    const float zeps = __ldg(zeps_p);
    const float sf   = __ldg(sf_p);
    const int G = gridDim.x;

    // producer: issue child+rels of tile t into stage s (t < ntiles guaranteed)
    auto issue = [&](int t, int s) {
        int q0 = t * QPT;
        int qn = nquads - q0; if (qn > QPT) qn = QPT;   // >0
        unsigned cb = smem_u32(&sStage[s][0]);
        unsigned mb = smem_u32(&sMbar[s]);
        unsigned cby = (unsigned)qn * 48u;
        unsigned rby = (unsigned)qn * 16u;
        mbar_expect_tx(mb, cby + rby);
        bulk_g2s(cb,           child + (size_t)q0 * 12, cby, mb);
        bulk_g2s(cb + C_BYTES, rels  + (size_t)q0 * 4,  rby, mb);
    };

    // prologue: fill both stages
    if (tid == 0) {
        if (blockIdx.x < ntiles)      issue(blockIdx.x, 0);
        if (blockIdx.x + G < ntiles)  issue(blockIdx.x + G, 1);
    }

    unsigned ph0 = 0, ph1 = 0;
    int s = 0;
    for (int t = blockIdx.x; t < ntiles; t += G) {
        int q = t * QPT + tid;
        bool act = q < nquads;

        // issue prnt LDGs FIRST — latency hides under the mbarrier wait
        float4 pA, pB, pC;
        if (act) {
            const float4 *p4 = reinterpret_cast<const float4 *>(prnt) + (size_t)q * 3;
            pA = __ldcs(p4 + 0); pB = __ldcs(p4 + 1); pC = __ldcs(p4 + 2);
        }

        unsigned mb = smem_u32(&sMbar[s]);
        if (s == 0) { mbar_wait(mb, ph0); ph0 ^= 1u; }
        else        { mbar_wait(mb, ph1); ph1 ^= 1u; }

        if (act) {
            const float4 *sc = reinterpret_cast<const float4 *>(&sStage[s][0]) + tid * 3;
            const int4  *sr  = reinterpret_cast<const int4 *>(&sStage[s][C_BYTES]) + tid;
            float4 cA = sc[0], cB = sc[1], cC = sc[2];
            int4 r4 = *sr;

            float pv[12] = {pA.x, pA.y, pA.z, pA.w, pB.x, pB.y, pB.z, pB.w,
                            pC.x, pC.y, pC.z, pC.w};
            float cv[12] = {cA.x, cA.y, cA.z, cA.w, cB.x, cB.y, cB.z, cB.w,
                            cC.x, cC.y, cC.z, cC.w};
            int rr[4] = {r4.x, r4.y, r4.z, r4.w};
            float ov[12];
#pragma unroll
            for (int i = 0; i < 4; i++) {
                row_compute(pv[3 * i], pv[3 * i + 1], pv[3 * i + 2],
                            cv[3 * i], cv[3 * i + 1], cv[3 * i + 2],
                            &sRel[rr[i] * REL_STRIDE4], zeps, sf,
                            ov[3 * i], ov[3 * i + 1], ov[3 * i + 2]);
            }
            float4 *o4 = reinterpret_cast<float4 *>(out) + (size_t)q * 3;
            __stcs(o4 + 0, make_float4(ov[0], ov[1], ov[2],  ov[3]));
            __stcs(o4 + 1, make_float4(ov[4], ov[5], ov[6],  ov[7]));
            __stcs(o4 + 2, make_float4(ov[8], ov[9], ov[10], ov[11]));
        }

        __syncthreads();   // whole CTA done reading stage s
        if (tid == 0 && t + 2 * G < ntiles) issue(t + 2 * G, s);
        s ^= 1;
    }

    // scalar tail (n % 4 rows) — empty for N = 8,000,000 but kept general
    int rem = n - nquads * 4;
    int gidx = blockIdx.x * TPB + tid;
    if (gidx < rem) {
        int i = nquads * 4 + gidx;
        float a0, a1, a2;
        row_compute(prnt[3 * i], prnt[3 * i + 1], prnt[3 * i + 2],
                    child[3 * i], child[3 * i + 1], child[3 * i + 2],
                    &sRel[rels[i] * REL_STRIDE4], zeps, sf, a0, a1, a2);
        out[3 * i] = a0; out[3 * i + 1] = a1; out[3 * i + 2] = a2;
    }
}

extern "C" void kernel_launch(void* const* d_in, const int* in_sizes, int n_in,
                              void* d_out, int out_size) {
    // metadata order: prnt_probs, child_probs, M, beta, z_epsilon, scale_factor, rels, var_sfx
    const float *prnt  = (const float *)d_in[0];
    const float *child = (const float *)d_in[1];
    const float *Mg    = (const float *)d_in[2];
    const float *betag = (const float *)d_in[3];
    const float *zeps  = (const float *)d_in[4];
    const float *sf    = (const float *)d_in[5];
    const int   *rels  = (const int *)d_in[6];
    float *out = (float *)d_out;

    int n = in_sizes[6];
    int nquads = n / 4;
    int ntiles = (nquads + QPT - 1) / QPT;
    int maxb = 148 * 5;   // 5 CTAs/SM residency target
    int blocks = ntiles < maxb ? (ntiles > 0 ? ntiles : 1) : maxb;

    alpha_kernel<<<blocks, TPB>>>(prnt, child, Mg, betag, zeps, sf, rels,
                                  out, n, nquads, ntiles);
}